// round 16
// baseline (speedup 1.0000x reference)
#include <cuda_runtime.h>
#include <cuda_fp16.h>
#include <cstdint>

#define NN 50000
#define EE 500000
#define FF 64
#define HH 4

// ---------------- scratch (device globals; no allocation allowed) ----------------
__device__ __align__(16) __half2 g_projh[(size_t)NN * 128]; // [n][h][f] fp16, 25.6 MB
__device__ __align__(16) float2  g_psum2[(size_t)NN * 32];  // [n][f] fp32 sum over heads
__device__ __align__(16) float g_sc[NN * 8];                // node scores [rad h0..3, tan h0..3]
__device__ __align__(16) float g_ssum[NN * 8];              // softmax denominators
__device__ __align__(16) float g_ex[(size_t)EE * 8];        // per-edge exp(logit)
__device__ __align__(16) float g_acc[NN * FF];              // scattered messages (head-mean folded)
__device__ __align__(16) float g_wrt[8 * 64];               // wrt[i][f], fp32 (logit path)

__device__ __forceinline__ void red_add_v4(float* p, float4 v) {
    asm volatile("red.global.add.v4.f32 [%0], {%1,%2,%3,%4};"
                 :: "l"(p), "f"(v.x), "f"(v.y), "f"(v.z), "f"(v.w) : "memory");
}

__device__ __forceinline__ float2 fma2(float2 a, float2 b, float2 c) {
    float2 d;
    asm("fma.rn.f32x2 %0, %1, %2, %3;"
        : "=l"(reinterpret_cast<unsigned long long&>(d))
        : "l"(reinterpret_cast<unsigned long long&>(a)),
          "l"(reinterpret_cast<unsigned long long&>(b)),
          "l"(reinterpret_cast<unsigned long long&>(c)));
    return d;
}

__device__ __forceinline__ void mma16816(float d[4],
                                         uint32_t a0, uint32_t a1, uint32_t a2, uint32_t a3,
                                         uint32_t b0, uint32_t b1) {
    asm volatile(
        "mma.sync.aligned.m16n8k16.row.col.f32.f16.f16.f32 "
        "{%0,%1,%2,%3}, {%4,%5,%6,%7}, {%8,%9}, {%0,%1,%2,%3};\n"
        : "+f"(d[0]), "+f"(d[1]), "+f"(d[2]), "+f"(d[3])
        : "r"(a0), "r"(a1), "r"(a2), "r"(a3), "r"(b0), "r"(b1));
}

// ---------------- init: zero accumulators; blocks 0-1 compute wrt (fp32) -------------
__global__ void init_kernel(const float* __restrict__ w_proj,
                            const float* __restrict__ rs,
                            const float* __restrict__ ts) {
    int i = blockIdx.x * blockDim.x + threadIdx.x;
    if (blockIdx.x < 2) {                 // i in [0,512): wrt[i>>6][i&63]
        int ii = i >> 6, f = i & 63;
        int h = ii & 3;
        const float* scv = (ii < 4) ? rs : ts;
        const float* wrow = w_proj + h * 4096 + f * 64;
        float s = 0.f;
        #pragma unroll 8
        for (int g = 0; g < 64; g++) s += wrow[g] * scv[h * 64 + g];
        g_wrt[i] = s;
    }
    int stride = gridDim.x * blockDim.x;
    for (int j = i; j < NN * FF; j += stride) g_acc[j] = 0.f;
    for (int j = i; j < NN * 8; j += stride) g_ssum[j] = 0.f;
}

// ---------------- proj via tensor cores (HMMA m16n8k16) + fp32 node scores ----------
// proj[n, h*64+g] = sum_f x[n,f]*W[h,f,g];  A = x (fp16), B = W^T stored [h][g][f] fp16.
// smem floats: [0,8192)=wh(32KB halves) [8192,10240)=xs32 [10240,11264)=xh(4KB halves)
//              [11264,15360)=outst(16KB halves) [15360,15880)=wrt padded  => 63520 B
__global__ void __launch_bounds__(256, 3)
proj_kernel(const float* __restrict__ x,
            const float* __restrict__ w_proj) {
    extern __shared__ float sh[];
    __half* wh    = (__half*)sh;                 // [4][64][64] wh[h][g*64+f]
    float*  xs32  = sh + 8192;                   // [32][64] fp32
    __half* xh    = (__half*)(sh + 10240);       // [32][64] fp16
    __half* outst = (__half*)(sh + 11264);       // [32][256] staging
    float*  wrtsh = sh + 15360;                  // [8][65] padded

    int tid = threadIdx.x;

    // weights: w_proj[h][f][g] fp32 -> wh[h][g][f] fp16 (transposed: B col-major)
    for (int idx = tid; idx < 16384; idx += 256) {
        int h = idx >> 12, rem = idx & 4095;
        int f = rem >> 6, g = rem & 63;
        wh[h * 4096 + g * 64 + f] = __float2half(w_proj[idx]);
    }
    // wrt (fp32) from global
    for (int e = tid; e < 512; e += 256) {
        int i = e >> 6, f = e & 63;
        wrtsh[i * 65 + f] = g_wrt[e];
    }

    int lane = tid & 31, w = tid >> 5;
    int h = w & 3, halfsel = w >> 2;          // warp: head h, node-half halfsel
    int g = lane >> 2, tg = lane & 3;
    int rowbase = halfsel * 16;
    const __half* whh = wh + h * 4096;

    int nd2 = tid >> 3, i2 = tid & 7;         // sc mapping: 256 threads = 32 nodes x 8
    int ntiles = (NN + 31) / 32;

    for (int tile = blockIdx.x; tile < ntiles; tile += gridDim.x) {
        int n0 = tile * 32;
        __syncthreads();   // also orders prologue (first iter) and outst reads (later iters)
        for (int idx = tid; idx < 2048; idx += 256) {
            int nd = idx >> 6, f = idx & 63;
            int n = n0 + nd;
            float v = (n < NN) ? x[n * 64 + f] : 0.f;
            xs32[idx] = v;
            xh[idx] = __float2half(v);
        }
        __syncthreads();

        // node scores (fp32 logit path)
        {
            int n2 = n0 + nd2;
            if (n2 < NN) {
                float s = 0.f;
                #pragma unroll 8
                for (int f = 0; f < 64; f++) s += xs32[nd2 * 64 + f] * wrtsh[i2 * 65 + f];
                g_sc[n2 * 8 + i2] = s;
            }
        }

        // tensor-core GEMM: warp computes 16 nodes x 64 outputs (one head)
        float d[8][4];
        #pragma unroll
        for (int nt = 0; nt < 8; nt++)
            #pragma unroll
            for (int k = 0; k < 4; k++) d[nt][k] = 0.f;

        #pragma unroll
        for (int ks = 0; ks < 4; ks++) {
            int r0 = rowbase + g, r1 = rowbase + g + 8;
            int c0 = ks * 16 + 2 * tg;
            uint32_t a0 = *(const uint32_t*)(xh + r0 * 64 + c0);
            uint32_t a1 = *(const uint32_t*)(xh + r1 * 64 + c0);
            uint32_t a2 = *(const uint32_t*)(xh + r0 * 64 + c0 + 8);
            uint32_t a3 = *(const uint32_t*)(xh + r1 * 64 + c0 + 8);
            #pragma unroll
            for (int nt = 0; nt < 8; nt++) {
                int ncol = nt * 8 + g;
                uint32_t b0 = *(const uint32_t*)(whh + ncol * 64 + c0);
                uint32_t b1 = *(const uint32_t*)(whh + ncol * 64 + c0 + 8);
                mma16816(d[nt], a0, a1, a2, a3, b0, b1);
            }
        }

        // D -> staging smem (rows rowbase+g / +8, cols h*64 + nt*8 + 2tg)
        #pragma unroll
        for (int nt = 0; nt < 8; nt++) {
            int col = h * 64 + nt * 8 + 2 * tg;
            __half2 lo = __floats2half2_rn(d[nt][0], d[nt][1]);
            __half2 hi = __floats2half2_rn(d[nt][2], d[nt][3]);
            *(__half2*)(outst + (rowbase + g) * 256 + col) = lo;
            *(__half2*)(outst + (rowbase + g + 8) * 256 + col) = hi;
        }
        __syncthreads();

        // coalesced projh store: 1024 uint4 (16B) chunks = 32 nodes x 512B
        for (int idx = tid; idx < 1024; idx += 256) {
            int nd = idx >> 5, c = idx & 31;
            int n = n0 + nd;
            if (n < NN)
                ((uint4*)g_projh)[(size_t)n * 32 + c] = *(const uint4*)(outst + nd * 256 + c * 8);
        }
        // psum: [n][f-pair] = sum_h outst[n][h*64 + 2fp..]
        for (int idx = tid; idx < 1024; idx += 256) {
            int nd = idx >> 5, fp = idx & 31;
            int n = n0 + nd;
            if (n < NN) {
                float2 s = make_float2(0.f, 0.f);
                #pragma unroll
                for (int hh = 0; hh < 4; hh++) {
                    float2 fv = __half22float2(*(const __half2*)(outst + nd * 256 + hh * 64 + fp * 2));
                    s.x += fv.x; s.y += fv.y;
                }
                g_psum2[(size_t)n * 32 + fp] = s;
            }
        }
    }
}

// ---------------- edge pass 1: exp(logits), accumulate softmax sums ----------------
__global__ void edge_pass1(const int* __restrict__ ei,
                           const float* __restrict__ elen,
                           const float* __restrict__ rds) {
    int i = blockIdx.x * blockDim.x + threadIdx.x;
    if (i >= EE) return;
    float scale = rds[0];
    int s = ei[i], r = ei[EE + i];
    const float4* scp = (const float4*)g_sc;
    float4 a0 = scp[s * 2], a1 = scp[s * 2 + 1];
    float4 b0 = scp[r * 2], b1 = scp[r * 2 + 1];
    float d = scale * elen[i];
    float4 er, et;
    er.x = __expf(a0.x - b0.x - d); er.y = __expf(a0.y - b0.y - d);
    er.z = __expf(a0.z - b0.z - d); er.w = __expf(a0.w - b0.w - d);
    et.x = __expf(a1.x - b1.x);     et.y = __expf(a1.y - b1.y);
    et.z = __expf(a1.z - b1.z);     et.w = __expf(a1.w - b1.w);
    float4* exp_ptr = (float4*)(g_ex + (size_t)i * 8);
    exp_ptr[0] = er;
    exp_ptr[1] = et;
    red_add_v4(g_ssum + r * 8, er);
    red_add_v4(g_ssum + r * 8 + 4, et);
}

// ---------------- edge pass 2: alpha-weighted scatter of fp16 sender proj ------------
// R6/R15 version (measured best): 8 lanes per edge, LDG.128 per head
__global__ void edge_pass2(const int* __restrict__ ei) {
    int lane = threadIdx.x & 31;
    int warp = (blockIdx.x * blockDim.x + threadIdx.x) >> 5;
    int grp = lane >> 3, sub = lane & 7;
    int e = warp * 4 + grp;
    if (e >= EE) return;
    int s = ei[e], r = ei[EE + e];

    float a = __fdividef(g_ex[(size_t)e * 8 + sub], g_ssum[r * 8 + sub]);
    const unsigned m = 0xffffffffu;
    float w0 = __shfl_sync(m, a, 0, 8) + __shfl_sync(m, a, 4, 8);
    float w1 = __shfl_sync(m, a, 1, 8) + __shfl_sync(m, a, 5, 8);
    float w2 = __shfl_sync(m, a, 2, 8) + __shfl_sync(m, a, 6, 8);
    float w3 = __shfl_sync(m, a, 3, 8) + __shfl_sync(m, a, 7, 8);

    const uint4* ph = (const uint4*)g_projh + (size_t)s * 32;
    uint4 q0 = ph[sub], q1 = ph[8 + sub], q2 = ph[16 + sub], q3 = ph[24 + sub];

    float v[8];
    #pragma unroll
    for (int k = 0; k < 8; k++) v[k] = 0.f;

    #pragma unroll
    for (int h = 0; h < 4; h++) {
        uint4 q = (h == 0) ? q0 : (h == 1) ? q1 : (h == 2) ? q2 : q3;
        float w = (h == 0) ? w0 : (h == 1) ? w1 : (h == 2) ? w2 : w3;
        float2 c0 = __half22float2(*(const __half2*)&q.x);
        float2 c1 = __half22float2(*(const __half2*)&q.y);
        float2 c2 = __half22float2(*(const __half2*)&q.z);
        float2 c3 = __half22float2(*(const __half2*)&q.w);
        v[0] += w * c0.x; v[1] += w * c0.y;
        v[2] += w * c1.x; v[3] += w * c1.y;
        v[4] += w * c2.x; v[5] += w * c2.y;
        v[6] += w * c3.x; v[7] += w * c3.y;
    }
    float4 vA = make_float4(0.25f * v[0], 0.25f * v[1], 0.25f * v[2], 0.25f * v[3]);
    float4 vB = make_float4(0.25f * v[4], 0.25f * v[5], 0.25f * v[6], 0.25f * v[7]);
    float* dst = g_acc + r * 64 + sub * 8;
    red_add_v4(dst, vA);
    red_add_v4(dst + 4, vB);
}

// ---------------- epilogue: msg, residual + out-GEMM (packed f32x2) ----------------
__global__ void epilogue_kernel(const float* __restrict__ x,
                                const float* __restrict__ w_out,
                                float* __restrict__ out) {
    __shared__ float2 wsh2[64 * 32];     // [f][gp]
    __shared__ float msh[8][4][64];
    int tid = threadIdx.x, lane = tid & 31, wid = tid >> 5;
    for (int idx = tid; idx < 2048; idx += 256) wsh2[idx] = ((const float2*)w_out)[idx];
    __syncthreads();

    int base = (blockIdx.x * 8 + wid) * 4;
    if (base >= NN) return;

    const float* psum = (const float*)g_psum2;
    #pragma unroll
    for (int j = 0; j < 4; j++) {
        int n = base + j;
        if (n >= NN) { msh[wid][j][lane] = 0.f; msh[wid][j][lane + 32] = 0.f; continue; }
        float ne = (g_ssum[n * 8] > 0.f) ? 0.5f : 0.f;
        #pragma unroll
        for (int k = 0; k < 2; k++) {
            int f = lane + k * 32;
            msh[wid][j][f] = g_acc[n * 64 + f] - ne * psum[(size_t)n * 64 + f];
        }
    }
    __syncwarp();

    float2 a2[4];
    #pragma unroll
    for (int j = 0; j < 4; j++) {
        int n = base + j;
        a2[j] = (n < NN) ? ((const float2*)x)[n * 32 + lane] : make_float2(0.f, 0.f);
    }
    #pragma unroll 4
    for (int f = 0; f < 64; f++) {
        float2 w = wsh2[f * 32 + lane];
        #pragma unroll
        for (int j = 0; j < 4; j++) {
            float m = msh[wid][j][f];
            a2[j] = fma2(w, make_float2(m, m), a2[j]);
        }
    }
    #pragma unroll
    for (int j = 0; j < 4; j++) {
        int n = base + j;
        if (n < NN) ((float2*)out)[n * 32 + lane] = a2[j];
    }
}

// ---------------- launch ----------------
extern "C" void kernel_launch(void* const* d_in, const int* in_sizes, int n_in,
                              void* d_out, int out_size) {
    const float* x      = (const float*)d_in[0];
    const int*   ei     = (const int*)d_in[1];
    // d_in[2] = edge_vec (unused by reference)
    const float* elen   = (const float*)d_in[3];
    const float* w_proj = (const float*)d_in[4];
    const float* rs     = (const float*)d_in[5];
    const float* ts     = (const float*)d_in[6];
    const float* rds    = (const float*)d_in[7];
    const float* w_out  = (const float*)d_in[8];
    float* out = (float*)d_out;

    const int shmem = 15880 * (int)sizeof(float);   // 63,520 B -> 3 blocks/SM
    cudaFuncSetAttribute(proj_kernel, cudaFuncAttributeMaxDynamicSharedMemorySize, shmem);

    init_kernel<<<512, 256>>>(w_proj, rs, ts);
    proj_kernel<<<444, 256, shmem>>>(x, w_proj);
    edge_pass1<<<(EE + 255) / 256, 256>>>(ei, elen, rds);
    edge_pass2<<<((EE / 4) * 32 + 255) / 256, 256>>>(ei);
    epilogue_kernel<<<(NN + 31) / 32, 256>>>(x, w_out, out);
}

// round 17
// speedup vs baseline: 1.4280x; 1.4280x over previous
#include <cuda_runtime.h>
#include <cuda_fp16.h>
#include <cstdint>

#define NN 50000
#define EE 500000
#define FF 64
#define HH 4

// ---------------- scratch (device globals; no allocation allowed) ----------------
__device__ __align__(16) __half2 g_projh[(size_t)NN * 128]; // [n][h][f] fp16, 25.6 MB
__device__ __align__(16) float2  g_psum2[(size_t)NN * 32];  // [n][f] fp32 sum over heads
__device__ __align__(16) float g_sc[NN * 8];                // node scores [rad h0..3, tan h0..3]
__device__ __align__(16) float g_ssum[NN * 8];              // softmax denominators
__device__ __align__(16) float g_ex[(size_t)EE * 8];        // per-edge exp(logit)
__device__ __align__(16) float g_acc[NN * FF];              // scattered messages (head-mean folded)
__device__ __align__(16) float g_wrt[8 * 64];               // wrt[i][f], fp32 (logit path)

__device__ __forceinline__ void red_add_v4(float* p, float4 v) {
    asm volatile("red.global.add.v4.f32 [%0], {%1,%2,%3,%4};"
                 :: "l"(p), "f"(v.x), "f"(v.y), "f"(v.z), "f"(v.w) : "memory");
}

__device__ __forceinline__ float2 fma2(float2 a, float2 b, float2 c) {
    float2 d;
    asm("fma.rn.f32x2 %0, %1, %2, %3;"
        : "=l"(reinterpret_cast<unsigned long long&>(d))
        : "l"(reinterpret_cast<unsigned long long&>(a)),
          "l"(reinterpret_cast<unsigned long long&>(b)),
          "l"(reinterpret_cast<unsigned long long&>(c)));
    return d;
}

__device__ __forceinline__ void mma16816(float d[4],
                                         uint32_t a0, uint32_t a1, uint32_t a2, uint32_t a3,
                                         uint32_t b0, uint32_t b1) {
    asm volatile(
        "mma.sync.aligned.m16n8k16.row.col.f32.f16.f16.f32 "
        "{%0,%1,%2,%3}, {%4,%5,%6,%7}, {%8,%9}, {%0,%1,%2,%3};\n"
        : "+f"(d[0]), "+f"(d[1]), "+f"(d[2]), "+f"(d[3])
        : "r"(a0), "r"(a1), "r"(a2), "r"(a3), "r"(b0), "r"(b1));
}

// ---------------- init: zero accumulators; blocks 0-1 compute wrt (fp32) -------------
__global__ void init_kernel(const float* __restrict__ w_proj,
                            const float* __restrict__ rs,
                            const float* __restrict__ ts) {
    int i = blockIdx.x * blockDim.x + threadIdx.x;
    if (blockIdx.x < 2) {                 // i in [0,512): wrt[i>>6][i&63]
        int ii = i >> 6, f = i & 63;
        int h = ii & 3;
        const float* scv = (ii < 4) ? rs : ts;
        const float* wrow = w_proj + h * 4096 + f * 64;
        float s = 0.f;
        #pragma unroll 8
        for (int g = 0; g < 64; g++) s += wrow[g] * scv[h * 64 + g];
        g_wrt[i] = s;
    }
    int stride = gridDim.x * blockDim.x;
    for (int j = i; j < NN * FF; j += stride) g_acc[j] = 0.f;
    for (int j = i; j < NN * 8; j += stride) g_ssum[j] = 0.f;
}

// ---------------- proj via tensor cores (HMMA m16n8k16), bank-conflict-free ---------
// proj[n, h*64+g] = sum_f x[n,f]*W[h,f,g];  A = x (fp16), B = W^T stored [h][g][f+pad].
// All hot smem row strides padded off multiples of 128B:
//   wh [4][64][72] halves, xh [32][72] halves, outst [32][264] halves, xs32 [32][65] fl
// smem floats: wh [0,9216) | xs32 [9216,11296) | xh [11296,12448) |
//              outst [12448,16672) | wrt [16672,17192)  => 68768 B -> 3 blocks/SM
#define XH_STR 72
#define WH_STR 72
#define OUT_STR 264
__global__ void __launch_bounds__(256, 3)
proj_kernel(const float* __restrict__ x,
            const float* __restrict__ w_proj) {
    extern __shared__ float sh[];
    __half* wh    = (__half*)sh;                 // [4][64][WH_STR] wh[h][g][f]
    float*  xs32  = sh + 9216;                   // [32][65] fp32 (padded)
    __half* xh    = (__half*)(sh + 11296);       // [32][XH_STR] fp16
    __half* outst = (__half*)(sh + 12448);       // [32][OUT_STR] staging
    float*  wrtsh = sh + 16672;                  // [8][65] padded

    int tid = threadIdx.x;

    // weights: w_proj[h][f][g] fp32 -> wh[h][g][f] fp16 (transposed: B col-major)
    for (int idx = tid; idx < 16384; idx += 256) {
        int h = idx >> 12, rem = idx & 4095;
        int f = rem >> 6, g = rem & 63;
        wh[h * 64 * WH_STR + g * WH_STR + f] = __float2half(w_proj[idx]);
    }
    // wrt (fp32) from global
    for (int e = tid; e < 512; e += 256) {
        int i = e >> 6, f = e & 63;
        wrtsh[i * 65 + f] = g_wrt[e];
    }

    int lane = tid & 31, w = tid >> 5;
    int h = w & 3, halfsel = w >> 2;          // warp: head h, node-half halfsel
    int g = lane >> 2, tg = lane & 3;
    int rowbase = halfsel * 16;
    const __half* whh = wh + h * 64 * WH_STR;

    int nd2 = tid >> 3, i2 = tid & 7;         // sc mapping: 256 threads = 32 nodes x 8
    int ntiles = (NN + 31) / 32;

    for (int tile = blockIdx.x; tile < ntiles; tile += gridDim.x) {
        int n0 = tile * 32;
        __syncthreads();   // orders prologue (first iter) and outst reads (later iters)
        for (int idx = tid; idx < 2048; idx += 256) {
            int nd = idx >> 6, f = idx & 63;
            int n = n0 + nd;
            float v = (n < NN) ? x[n * 64 + f] : 0.f;
            xs32[nd * 65 + f] = v;
            xh[nd * XH_STR + f] = __float2half(v);
        }
        __syncthreads();

        // node scores (fp32 logit path)
        {
            int n2 = n0 + nd2;
            if (n2 < NN) {
                float s = 0.f;
                #pragma unroll 8
                for (int f = 0; f < 64; f++) s += xs32[nd2 * 65 + f] * wrtsh[i2 * 65 + f];
                g_sc[n2 * 8 + i2] = s;
            }
        }

        // tensor-core GEMM: warp computes 16 nodes x 64 outputs (one head)
        float d[8][4];
        #pragma unroll
        for (int nt = 0; nt < 8; nt++)
            #pragma unroll
            for (int k = 0; k < 4; k++) d[nt][k] = 0.f;

        #pragma unroll
        for (int ks = 0; ks < 4; ks++) {
            int r0 = rowbase + g, r1 = rowbase + g + 8;
            int c0 = ks * 16 + 2 * tg;
            uint32_t a0 = *(const uint32_t*)(xh + r0 * XH_STR + c0);
            uint32_t a1 = *(const uint32_t*)(xh + r1 * XH_STR + c0);
            uint32_t a2 = *(const uint32_t*)(xh + r0 * XH_STR + c0 + 8);
            uint32_t a3 = *(const uint32_t*)(xh + r1 * XH_STR + c0 + 8);
            #pragma unroll
            for (int nt = 0; nt < 8; nt++) {
                int ncol = nt * 8 + g;
                uint32_t b0 = *(const uint32_t*)(whh + ncol * WH_STR + c0);
                uint32_t b1 = *(const uint32_t*)(whh + ncol * WH_STR + c0 + 8);
                mma16816(d[nt], a0, a1, a2, a3, b0, b1);
            }
        }

        // D -> staging smem (rows rowbase+g / +8, cols h*64 + nt*8 + 2tg)
        #pragma unroll
        for (int nt = 0; nt < 8; nt++) {
            int col = h * 64 + nt * 8 + 2 * tg;
            __half2 lo = __floats2half2_rn(d[nt][0], d[nt][1]);
            __half2 hi = __floats2half2_rn(d[nt][2], d[nt][3]);
            *(__half2*)(outst + (rowbase + g) * OUT_STR + col) = lo;
            *(__half2*)(outst + (rowbase + g + 8) * OUT_STR + col) = hi;
        }
        __syncthreads();

        // coalesced projh store: 1024 uint4 (16B) chunks = 32 nodes x 512B
        for (int idx = tid; idx < 1024; idx += 256) {
            int nd = idx >> 5, c = idx & 31;
            int n = n0 + nd;
            if (n < NN)
                ((uint4*)g_projh)[(size_t)n * 32 + c] =
                    *(const uint4*)(outst + nd * OUT_STR + c * 8);
        }
        // psum: [n][f-pair] = sum_h outst[n][h*64 + 2fp..]
        for (int idx = tid; idx < 1024; idx += 256) {
            int nd = idx >> 5, fp = idx & 31;
            int n = n0 + nd;
            if (n < NN) {
                float2 s = make_float2(0.f, 0.f);
                #pragma unroll
                for (int hh = 0; hh < 4; hh++) {
                    float2 fv = __half22float2(
                        *(const __half2*)(outst + nd * OUT_STR + hh * 64 + fp * 2));
                    s.x += fv.x; s.y += fv.y;
                }
                g_psum2[(size_t)n * 32 + fp] = s;
            }
        }
    }
}

// ---------------- edge pass 1: exp(logits), accumulate softmax sums ----------------
__global__ void edge_pass1(const int* __restrict__ ei,
                           const float* __restrict__ elen,
                           const float* __restrict__ rds) {
    int i = blockIdx.x * blockDim.x + threadIdx.x;
    if (i >= EE) return;
    float scale = rds[0];
    int s = ei[i], r = ei[EE + i];
    const float4* scp = (const float4*)g_sc;
    float4 a0 = scp[s * 2], a1 = scp[s * 2 + 1];
    float4 b0 = scp[r * 2], b1 = scp[r * 2 + 1];
    float d = scale * elen[i];
    float4 er, et;
    er.x = __expf(a0.x - b0.x - d); er.y = __expf(a0.y - b0.y - d);
    er.z = __expf(a0.z - b0.z - d); er.w = __expf(a0.w - b0.w - d);
    et.x = __expf(a1.x - b1.x);     et.y = __expf(a1.y - b1.y);
    et.z = __expf(a1.z - b1.z);     et.w = __expf(a1.w - b1.w);
    float4* exp_ptr = (float4*)(g_ex + (size_t)i * 8);
    exp_ptr[0] = er;
    exp_ptr[1] = et;
    red_add_v4(g_ssum + r * 8, er);
    red_add_v4(g_ssum + r * 8 + 4, et);
}

// ---------------- edge pass 2: alpha-weighted scatter of fp16 sender proj ------------
// R6/R15 version (measured best): 8 lanes per edge, LDG.128 per head
__global__ void edge_pass2(const int* __restrict__ ei) {
    int lane = threadIdx.x & 31;
    int warp = (blockIdx.x * blockDim.x + threadIdx.x) >> 5;
    int grp = lane >> 3, sub = lane & 7;
    int e = warp * 4 + grp;
    if (e >= EE) return;
    int s = ei[e], r = ei[EE + e];

    float a = __fdividef(g_ex[(size_t)e * 8 + sub], g_ssum[r * 8 + sub]);
    const unsigned m = 0xffffffffu;
    float w0 = __shfl_sync(m, a, 0, 8) + __shfl_sync(m, a, 4, 8);
    float w1 = __shfl_sync(m, a, 1, 8) + __shfl_sync(m, a, 5, 8);
    float w2 = __shfl_sync(m, a, 2, 8) + __shfl_sync(m, a, 6, 8);
    float w3 = __shfl_sync(m, a, 3, 8) + __shfl_sync(m, a, 7, 8);

    const uint4* ph = (const uint4*)g_projh + (size_t)s * 32;
    uint4 q0 = ph[sub], q1 = ph[8 + sub], q2 = ph[16 + sub], q3 = ph[24 + sub];

    float v[8];
    #pragma unroll
    for (int k = 0; k < 8; k++) v[k] = 0.f;

    #pragma unroll
    for (int h = 0; h < 4; h++) {
        uint4 q = (h == 0) ? q0 : (h == 1) ? q1 : (h == 2) ? q2 : q3;
        float w = (h == 0) ? w0 : (h == 1) ? w1 : (h == 2) ? w2 : w3;
        float2 c0 = __half22float2(*(const __half2*)&q.x);
        float2 c1 = __half22float2(*(const __half2*)&q.y);
        float2 c2 = __half22float2(*(const __half2*)&q.z);
        float2 c3 = __half22float2(*(const __half2*)&q.w);
        v[0] += w * c0.x; v[1] += w * c0.y;
        v[2] += w * c1.x; v[3] += w * c1.y;
        v[4] += w * c2.x; v[5] += w * c2.y;
        v[6] += w * c3.x; v[7] += w * c3.y;
    }
    float4 vA = make_float4(0.25f * v[0], 0.25f * v[1], 0.25f * v[2], 0.25f * v[3]);
    float4 vB = make_float4(0.25f * v[4], 0.25f * v[5], 0.25f * v[6], 0.25f * v[7]);
    float* dst = g_acc + r * 64 + sub * 8;
    red_add_v4(dst, vA);
    red_add_v4(dst + 4, vB);
}

// ---------------- epilogue: msg, residual + out-GEMM (packed f32x2) ----------------
__global__ void epilogue_kernel(const float* __restrict__ x,
                                const float* __restrict__ w_out,
                                float* __restrict__ out) {
    __shared__ float2 wsh2[64 * 32];     // [f][gp]
    __shared__ float msh[8][4][64];
    int tid = threadIdx.x, lane = tid & 31, wid = tid >> 5;
    for (int idx = tid; idx < 2048; idx += 256) wsh2[idx] = ((const float2*)w_out)[idx];
    __syncthreads();

    int base = (blockIdx.x * 8 + wid) * 4;
    if (base >= NN) return;

    const float* psum = (const float*)g_psum2;
    #pragma unroll
    for (int j = 0; j < 4; j++) {
        int n = base + j;
        if (n >= NN) { msh[wid][j][lane] = 0.f; msh[wid][j][lane + 32] = 0.f; continue; }
        float ne = (g_ssum[n * 8] > 0.f) ? 0.5f : 0.f;
        #pragma unroll
        for (int k = 0; k < 2; k++) {
            int f = lane + k * 32;
            msh[wid][j][f] = g_acc[n * 64 + f] - ne * psum[(size_t)n * 64 + f];
        }
    }
    __syncwarp();

    float2 a2[4];
    #pragma unroll
    for (int j = 0; j < 4; j++) {
        int n = base + j;
        a2[j] = (n < NN) ? ((const float2*)x)[n * 32 + lane] : make_float2(0.f, 0.f);
    }
    #pragma unroll 4
    for (int f = 0; f < 64; f++) {
        float2 w = wsh2[f * 32 + lane];
        #pragma unroll
        for (int j = 0; j < 4; j++) {
            float m = msh[wid][j][f];
            a2[j] = fma2(w, make_float2(m, m), a2[j]);
        }
    }
    #pragma unroll
    for (int j = 0; j < 4; j++) {
        int n = base + j;
        if (n < NN) ((float2*)out)[n * 32 + lane] = a2[j];
    }
}

// ---------------- launch ----------------
extern "C" void kernel_launch(void* const* d_in, const int* in_sizes, int n_in,
                              void* d_out, int out_size) {
    const float* x      = (const float*)d_in[0];
    const int*   ei     = (const int*)d_in[1];
    // d_in[2] = edge_vec (unused by reference)
    const float* elen   = (const float*)d_in[3];
    const float* w_proj = (const float*)d_in[4];
    const float* rs     = (const float*)d_in[5];
    const float* ts     = (const float*)d_in[6];
    const float* rds    = (const float*)d_in[7];
    const float* w_out  = (const float*)d_in[8];
    float* out = (float*)d_out;

    const int shmem = 17192 * (int)sizeof(float);   // 68,768 B -> 3 blocks/SM
    cudaFuncSetAttribute(proj_kernel, cudaFuncAttributeMaxDynamicSharedMemorySize, shmem);

    init_kernel<<<512, 256>>>(w_proj, rs, ts);
    proj_kernel<<<444, 256, shmem>>>(x, w_proj);
    edge_pass1<<<(EE + 255) / 256, 256>>>(ei, elen, rds);
    edge_pass2<<<((EE / 4) * 32 + 255) / 256, 256>>>(ei);
    epilogue_kernel<<<(NN + 31) / 32, 256>>>(x, w_out, out);
}